// round 15
// baseline (speedup 1.0000x reference)
#include <cuda_runtime.h>
#include <cuda_bf16.h>
#include <cuda_fp16.h>
#include <cuda_fp8.h>
#include <cstdint>

// Problem constants (fixed shape: path_fea [131072, 64, 1, 1, 2] fp32)
#define GNUM 8192        // groups = B / 16
#define PNUM 16          // samples per group
#define DNUM 128         // feature dim
#define KSUB 64          // screening subset: first 64 dims (d^2 >= d^2_sub)
#define NTILE 64         // GNUM / 128 (M tiles)
#define NBJ 32           // GNUM / 256 (N tiles)
#define NTILES_W 1056    // sum_{ti} (32 - ti/2): 128x256 triangular tiles
#define GRID_B 296       // persistent CTAs (148 SMs * 2)
#define TROW 80          // smem tile row stride in bytes (64 fp8 + 16 pad)
#define TILEA (128 * TROW)   // 10240 B
#define TILEB_SZ (256 * TROW)  // 20480 B

// -------- device scratch (no allocs allowed) --------
__device__ uint8_t g_centerF8[GNUM * KSUB];   // e4m3 centers, first 64 dims
__device__ __half  g_centerHf[GNUM * DNUM];   // fp16 centers (exact fallback)
__device__ __half  g_q64h[GNUM];              // partial ||c||^2 over first 64 dims
__device__ float g_intra_part[GNUM];
__device__ float g_inter_part[GRID_B];
__device__ unsigned int g_done = 0;           // self-resetting

// ===================== helpers =====================
__device__ __forceinline__ uint32_t smem_u32(const void* p) {
    uint32_t a;
    asm("{ .reg .u64 t; cvta.to.shared.u64 t, %1; cvt.u32.u64 %0, t; }"
        : "=r"(a) : "l"(p));
    return a;
}
__device__ __forceinline__ void cp16(uint32_t dst, const void* src) {
    asm volatile("cp.async.cg.shared.global [%0], [%1], 16;"
                 :: "r"(dst), "l"(src) : "memory");
}
__device__ __forceinline__ void cp_commit() {
    asm volatile("cp.async.commit_group;" ::: "memory");
}
__device__ __forceinline__ void cp_wait0() {
    asm volatile("cp.async.wait_group 0;" ::: "memory");
}
__device__ __forceinline__ void ldm_x4_raw(uint32_t (&r)[4], uint32_t addr) {
    asm volatile("ldmatrix.sync.aligned.m8n8.x4.shared.b16 {%0,%1,%2,%3}, [%4];"
        : "=r"(r[0]), "=r"(r[1]), "=r"(r[2]), "=r"(r[3]) : "r"(addr));
}
// FP8 e4m3 MMA with f16 accumulators
__device__ __forceinline__ void mma_fp8_h(uint32_t (&d)[2], const uint32_t (&a)[4],
                                          uint32_t b0, uint32_t b1) {
    asm volatile(
        "mma.sync.aligned.m16n8k32.row.col.f16.e4m3.e4m3.f16 "
        "{%0,%1}, {%2,%3,%4,%5}, {%6,%7}, {%0,%1};"
        : "+r"(d[0]), "+r"(d[1])
        : "r"(a[0]), "r"(a[1]), "r"(a[2]), "r"(a[3]), "r"(b0), "r"(b1));
}

// ============================================================
// Kernel A: per-group center + intra hinge + fp8(first 64 dims) +
// fp16 centers + q64 table (memory-bound, wide grid)
// ============================================================
__global__ void __launch_bounds__(512) center_intra_kernel(const float* __restrict__ fea) {
    __shared__ float sf[PNUM * DNUM];
    __shared__ float sc[DNUM];
    __shared__ float s_red[4];
    __shared__ float s_h[PNUM];

    const int g = blockIdx.x;
    const int tid = threadIdx.x;

    const float4* base4 = (const float4*)(fea + (size_t)g * (PNUM * DNUM));
    ((float4*)sf)[tid] = base4[tid];
    __syncthreads();

    float c = 0.0f;
    if (tid < DNUM) {
        #pragma unroll
        for (int s = 0; s < PNUM; s++) c += sf[s * DNUM + tid];
        c *= (1.0f / PNUM);
        sc[tid] = c;
        g_centerHf[(size_t)g * DNUM + tid] = __float2half(c);
        if (tid < KSUB)
            g_centerF8[(size_t)g * KSUB + tid] =
                (uint8_t)__nv_cvt_float_to_fp8(c, __NV_SATFINITE, __NV_E4M3);
    }
    float cs = (tid < DNUM) ? c * c : 0.0f;
    #pragma unroll
    for (int o = 16; o > 0; o >>= 1) cs += __shfl_down_sync(0xffffffffu, cs, o);
    if (tid < DNUM && (tid & 31) == 0) s_red[tid >> 5] = cs;
    __syncthreads();
    if (tid == 0)
        g_q64h[g] = __float2half(s_red[0] + s_red[1]);   // dims 0..63

    const int w = tid >> 5, l = tid & 31;
    float acc = 0.0f;
    #pragma unroll
    for (int q = 0; q < 4; q++) {
        int dd = l + 32 * q;
        float df = sf[w * DNUM + dd] - sc[dd];
        acc += df * df;
    }
    #pragma unroll
    for (int o = 16; o > 0; o >>= 1) acc += __shfl_down_sync(0xffffffffu, acc, o);
    if (l == 0) {
        float d = fmaxf(sqrtf(acc) - 0.1f, 0.0f);
        s_h[w] = d * d;
    }
    __syncthreads();
    if (tid == 0) {
        float t = 0.0f;
        #pragma unroll
        for (int s = 0; s < PNUM; s++) t += s_h[s];
        g_intra_part[g] = t;
    }
}

// ============================================================
// Kernel B: persistent FP8 half-Gram SYRK, 128x256 tiles (K=64),
// f16 accumulators, A+B double-buffered, per-element half2 screen at
// d2_64 >= 2, exact fp16 fallback, fused finalize (last CTA).
// Tile map: ti in [0,64), bj in [ti/2, 32). 1056 tiles.
// ============================================================
__global__ void __launch_bounds__(256, 2) gram_finalize_kernel(float* __restrict__ out) {
    extern __shared__ uint8_t sm[];
    uint8_t* bufA[2] = { sm, sm + TILEA };
    uint8_t* bufB[2] = { sm + 2 * TILEA, sm + 2 * TILEA + TILEB_SZ };

    __shared__ float s_red[8];
    __shared__ unsigned s_last;

    const int tid = threadIdx.x;
    const int wid = tid >> 5, lane = tid & 31;

    const int t0 = (int)(((long long)blockIdx.x * NTILES_W) / GRID_B);
    const int t1 = (int)(((long long)(blockIdx.x + 1) * NTILES_W) / GRID_B);

    int ti = 0, rowoff = 0;
    while (t0 >= rowoff + (NBJ - (ti >> 1))) { rowoff += NBJ - (ti >> 1); ti++; }
    int bj = (ti >> 1) + (t0 - rowoff);

    const uint8_t* gcb = g_centerF8;
    auto load_tileA = [&](uint8_t* dst, int g0) {
        #pragma unroll
        for (int i = 0; i < 2; i++) {
            int u = tid + 256 * i;
            int r = u >> 2, c16 = (u & 3) * 16;
            cp16(smem_u32(dst + r * TROW + c16),
                 gcb + (size_t)(g0 + r) * KSUB + c16);
        }
    };
    auto load_tileB = [&](uint8_t* dst, int g0) {
        #pragma unroll
        for (int i = 0; i < 4; i++) {
            int u = tid + 256 * i;
            int r = u >> 2, c16 = (u & 3) * 16;
            cp16(smem_u32(dst + r * TROW + c16),
                 gcb + (size_t)(g0 + r) * KSUB + c16);
        }
    };

    // prologue loads
    load_tileA(bufA[0], ti * 128);
    load_tileB(bufB[0], bj * 256);
    cp_commit();

    const int wm = wid & 1;            // 2 warps along M (64 rows)
    const int wn = wid >> 1;           // 4 warps along N (64 cols each)
    const int lrow = lane & 15;
    const int lcolB = (lane >> 4) * 16;
    const int r_l = lane >> 2;
    const int c_l = 2 * (lane & 3);

    const uint32_t aBase[2] = {
        smem_u32(bufA[0]) + (64 * wm + lrow) * TROW + lcolB,
        smem_u32(bufA[1]) + (64 * wm + lrow) * TROW + lcolB };
    const uint32_t bBase[2] = {
        smem_u32(bufB[0]) + (64 * wn + lrow) * TROW + lcolB,
        smem_u32(bufB[1]) + (64 * wn + lrow) * TROW + lcolB };

    const __half2 neg2 = __float2half2_rn(-2.0f);

    int aCur = 0, bCur = 0;
    float lsum = 0.0f;

    for (int t = t0; t < t1; t++) {
        const int i0 = ti * 128, j0 = bj * 256;
        cp_wait0();
        __syncthreads();

        int nti = ti, nbj = bj + 1;
        if (nbj == NBJ) { nti = ti + 1; nbj = nti >> 1; }
        const bool havenext = (t + 1 < t1);
        const bool newrow = (nti != ti);
        if (havenext) {
            if (newrow) load_tileA(bufA[aCur ^ 1], nti * 128);
            load_tileB(bufB[bCur ^ 1], nbj * 256);
            cp_commit();
        }

        // ---- compute 128x256 half-Gram tile: 2 k-steps of k32 ----
        const uint32_t aB = aBase[aCur];
        const uint32_t bB = bBase[bCur];
        uint32_t acc[4][8][2];
        #pragma unroll
        for (int mt = 0; mt < 4; mt++)
            #pragma unroll
            for (int nt = 0; nt < 8; nt++) { acc[mt][nt][0] = 0u; acc[mt][nt][1] = 0u; }

        #pragma unroll
        for (int ks = 0; ks < 2; ks++) {
            const int kb = ks * 32;
            uint32_t a[4][4];
            #pragma unroll
            for (int mt = 0; mt < 4; mt++)
                ldm_x4_raw(a[mt], aB + mt * (16 * TROW) + kb);
            uint32_t bq[4][4];
            #pragma unroll
            for (int q = 0; q < 4; q++)
                ldm_x4_raw(bq[q], bB + q * (16 * TROW) + kb);

            #pragma unroll
            for (int mt = 0; mt < 4; mt++) {
                #pragma unroll
                for (int nt = 0; nt < 8; nt++) {
                    const int q = nt >> 1;
                    const int sel = nt & 1;
                    mma_fp8_h(acc[mt][nt], a[mt], bq[q][sel], bq[q][sel + 2]);
                }
            }
        }

        // ---- epilogue: per-element screen  d2_64 = qa+qb-2g >= 2.0 ----
        const bool diag = (bj == (ti >> 1));

        __half2 qa2[8];
        #pragma unroll
        for (int mt = 0; mt < 4; mt++) {
            const int li0 = i0 + 64 * wm + 16 * mt + r_l;
            qa2[2 * mt]     = __half2half2(__ldg(&g_q64h[li0]));
            qa2[2 * mt + 1] = __half2half2(__ldg(&g_q64h[li0 + 8]));
        }
        __half2 qb2[8];
        #pragma unroll
        for (int nt = 0; nt < 8; nt++)
            qb2[nt] = __ldg((const __half2*)&g_q64h[j0 + 64 * wn + 8 * nt + c_l]);

        __half2 mn2 = __float2half2_rn(60000.0f);
        #pragma unroll
        for (int mt = 0; mt < 4; mt++) {
            #pragma unroll
            for (int nt = 0; nt < 8; nt++) {
                __half2 s0 = __hadd2(qa2[2 * mt], qb2[nt]);
                __half2 s1 = __hadd2(qa2[2 * mt + 1], qb2[nt]);
                mn2 = __hmin2(mn2, __hfma2(*(const __half2*)&acc[mt][nt][0], neg2, s0));
                mn2 = __hmin2(mn2, __hfma2(*(const __half2*)&acc[mt][nt][1], neg2, s1));
            }
        }
        float fmn = fminf(__low2float(mn2), __high2float(mn2));

        if (diag || fmn < 2.0f) {
            // slow path: per-element exact check (diagonal / rare failures)
            #pragma unroll 1
            for (int mt = 0; mt < 4; mt++) {
                #pragma unroll 1
                for (int nt = 0; nt < 8; nt++) {
                    #pragma unroll 1
                    for (int rg = 0; rg < 2; rg++) {
                        float2 g2 = __half22float2(*(const __half2*)&acc[mt][nt][rg]);
                        float qaf = __low2float(qa2[2 * mt + rg]);
                        float2 qbf = __half22float2(qb2[nt]);
                        const int gi = i0 + 64 * wm + 16 * mt + r_l + 8 * rg;
                        #pragma unroll 1
                        for (int e = 0; e < 2; e++) {
                            const int gj = j0 + 64 * wn + 8 * nt + c_l + e;
                            float gval = e ? g2.y : g2.x;
                            float v = qaf + (e ? qbf.y : qbf.x) - 2.0f * gval;
                            if (v < 2.0f && gi < gj) {
                                // exact full-dim distance from fp16 centers
                                const __half2* ci = (const __half2*)&g_centerHf[(size_t)gi * DNUM];
                                const __half2* cj = (const __half2*)&g_centerHf[(size_t)gj * DNUM];
                                float d2 = 0.0f;
                                #pragma unroll 1
                                for (int k = 0; k < DNUM / 2; k++) {
                                    float2 av = __half22float2(ci[k]);
                                    float2 bv = __half22float2(cj[k]);
                                    float dx = av.x - bv.x, dy = av.y - bv.y;
                                    d2 += dx * dx + dy * dy;
                                }
                                if (d2 < 1.0f) {
                                    float d = sqrtf(fmaxf(d2, 0.0f));
                                    float h = 1.0f - d;
                                    lsum += h * h;
                                }
                            }
                        }
                    }
                }
            }
        }

        if (havenext) {
            if (newrow) aCur ^= 1;
            bCur ^= 1;
            ti = nti; bj = nbj;
        }
    }

    // per-CTA inter reduction
    #pragma unroll
    for (int o = 16; o > 0; o >>= 1) lsum += __shfl_down_sync(0xffffffffu, lsum, o);
    __syncthreads();
    if (lane == 0) s_red[wid] = lsum;
    __syncthreads();
    if (tid == 0) {
        float tsum = 0.0f;
        #pragma unroll
        for (int w = 0; w < 8; w++) tsum += s_red[w];
        g_inter_part[blockIdx.x] = tsum;
    }

    // last-CTA-done finalize
    __threadfence();
    __syncthreads();
    if (tid == 0) {
        unsigned v = atomicAdd(&g_done, 1u);
        s_last = (v == GRID_B - 1) ? 1u : 0u;
    }
    __syncthreads();
    if (s_last) {
        __threadfence();
        float a = 0.0f, b = 0.0f;
        for (int i = tid; i < GRID_B; i += 256) a += g_inter_part[i];
        for (int i = tid; i < GNUM; i += 256) b += g_intra_part[i];
        #pragma unroll
        for (int o = 16; o > 0; o >>= 1) {
            a += __shfl_down_sync(0xffffffffu, a, o);
            b += __shfl_down_sync(0xffffffffu, b, o);
        }
        __shared__ float fa[8], fb[8];
        if (lane == 0) { fa[wid] = a; fb[wid] = b; }
        __syncthreads();
        if (tid == 0) {
            float A = 0.0f, B = 0.0f;
            #pragma unroll
            for (int w = 0; w < 8; w++) { A += fa[w]; B += fb[w]; }
            out[0] = A / 33550336.0f;              // G*(G-1)/2
            out[1] = B / (float)(GNUM * PNUM);
            g_done = 0;                            // reset for next replay
        }
    }
}

extern "C" void kernel_launch(void* const* d_in, const int* in_sizes, int n_in,
                              void* d_out, int out_size) {
    const float* fea = (const float*)d_in[0];
    float* out = (float*)d_out;

    center_intra_kernel<<<GNUM, 512>>>(fea);

    const int smem_bytes = 2 * TILEA + 2 * TILEB_SZ;   // 61440
    cudaFuncSetAttribute(gram_finalize_kernel,
                         cudaFuncAttributeMaxDynamicSharedMemorySize, smem_bytes);
    gram_finalize_kernel<<<GRID_B, 256, smem_bytes>>>(out);
}